// round 1
// baseline (speedup 1.0000x reference)
#include <cuda_runtime.h>
#include <cuda_bf16.h>
#include <cstdint>

// Problem constants (shapes are fixed by the dataset).
static constexpr int NN    = 50000;      // nodes
static constexpr int HIDC  = 64;         // hidden/z dim
static constexpr int INDIM = 128;
static constexpr int N64   = NN * HIDC;  // 3,200,000

// --- zeroed scratch region (one contiguous array so a single kernel clears it) ---
static constexpr long long OFF_AGG1 = 0;                 // [N64]   layer1 aggregate
static constexpr long long OFF_A0   = OFF_AGG1 + N64;    // [N64]   layer2 mu aggregate
static constexpr long long OFF_A1   = OFF_A0 + N64;      // [N64]   layer2 sig aggregate
static constexpr long long OFF_SUMS = OFF_A1 + N64;      // [2*64*64] pooled sums
static constexpr long long OFF_CNT  = OFF_SUMS + 2*64*64;// [64]    per-graph counts
static constexpr long long OFF_DEG  = OFF_CNT + 64;      // [NN]    degree (float)
static constexpr long long ZTOT     = OFF_DEG + NN;      // total floats (divisible by 4)

__device__ float g_zero[ZTOT];

// --- non-zeroed scratch ---
__device__ float g_XW[N64];     // x @ W1
__device__ float g_h1[N64];     // ELU(conv1)
__device__ float g_T[2 * N64];  // h1 @ Wmu, h1 @ Wsig
__device__ float g_dinv[NN];    // rsqrt(deg)

// ---------------- helpers ----------------
__device__ __forceinline__ void red_add_f32x4(float* p, float4 v) {
    asm volatile("red.global.add.v4.f32 [%0], {%1,%2,%3,%4};"
                 :: "l"(p), "f"(v.x), "f"(v.y), "f"(v.z), "f"(v.w) : "memory");
}
__device__ __forceinline__ void red_add_f32(float* p, float v) {
    asm volatile("red.global.add.f32 [%0], %1;" :: "l"(p), "f"(v) : "memory");
}
__device__ __forceinline__ float elu1(float x) {
    return x > 0.0f ? x : expm1f(x);
}
__device__ __forceinline__ float4 elu4(float4 v) {
    v.x = elu1(v.x); v.y = elu1(v.y); v.z = elu1(v.z); v.w = elu1(v.w);
    return v;
}

// ---------------- kernels ----------------

__global__ void k_zero() {
    long long i = (long long)blockIdx.x * blockDim.x + threadIdx.x;
    long long n4 = ZTOT / 4;
    if (i < n4) reinterpret_cast<float4*>(g_zero)[i] = make_float4(0.f, 0.f, 0.f, 0.f);
}

__global__ void k_deg(const int* __restrict__ dst, int E) {
    int e = blockIdx.x * blockDim.x + threadIdx.x;
    if (e < E) red_add_f32(&g_zero[OFF_DEG + dst[e]], 1.0f);
}

__global__ void k_dinv(int N) {
    int i = blockIdx.x * blockDim.x + threadIdx.x;
    if (i < N) g_dinv[i] = rsqrtf(g_zero[OFF_DEG + i] + 1.0f);  // +1 self loop
}

// GEMM1: X[N,128] @ W[128,64] -> g_XW[N,64]
// block = 128 threads, 32 rows/block; thread = (rg 0..7, q 0..15): 4 rows x 4 cols.
__global__ void k_gemm1(const float* __restrict__ X, const float* __restrict__ W, int N) {
    __shared__ float Ws[INDIM * HIDC];
    for (int i = threadIdx.x; i < INDIM * HIDC / 4; i += 128)
        reinterpret_cast<float4*>(Ws)[i] = reinterpret_cast<const float4*>(W)[i];
    __syncthreads();

    const int q  = threadIdx.x & 15;
    const int rg = threadIdx.x >> 4;
    const int row0 = blockIdx.x * 32;

    float4 acc[4];
    int rows[4]; bool valid[4];
#pragma unroll
    for (int rr = 0; rr < 4; rr++) {
        rows[rr] = row0 + rg + 8 * rr;
        valid[rr] = rows[rr] < N;
        acc[rr] = make_float4(0.f, 0.f, 0.f, 0.f);
    }

    for (int k4 = 0; k4 < INDIM / 4; k4++) {
        float4 a[4];
#pragma unroll
        for (int rr = 0; rr < 4; rr++)
            a[rr] = valid[rr]
                ? reinterpret_cast<const float4*>(&X[(long long)rows[rr] * INDIM + k4 * 4])[0]
                : make_float4(0.f, 0.f, 0.f, 0.f);
#pragma unroll
        for (int kk = 0; kk < 4; kk++) {
            float4 w = reinterpret_cast<const float4*>(&Ws[(k4 * 4 + kk) * HIDC + q * 4])[0];
#pragma unroll
            for (int rr = 0; rr < 4; rr++) {
                float av = (&a[rr].x)[kk];
                acc[rr].x += av * w.x; acc[rr].y += av * w.y;
                acc[rr].z += av * w.z; acc[rr].w += av * w.w;
            }
        }
    }
#pragma unroll
    for (int rr = 0; rr < 4; rr++)
        if (valid[rr])
            reinterpret_cast<float4*>(&g_XW[(long long)rows[rr] * HIDC + q * 4])[0] = acc[rr];
}

// Layer-1 edge aggregation: 16 threads/edge, vector reductions.
__global__ void k_agg1(const int* __restrict__ src, const int* __restrict__ dst, int E) {
    long long idx = (long long)blockIdx.x * blockDim.x + threadIdx.x;
    if (idx >= (long long)E * 16) return;
    int e = (int)(idx >> 4);
    int c = (int)(idx & 15);
    int s = src[e], d = dst[e];
    float norm = g_dinv[s] * g_dinv[d];
    float4 v = reinterpret_cast<const float4*>(&g_XW[(long long)s * HIDC + c * 4])[0];
    v.x *= norm; v.y *= norm; v.z *= norm; v.w *= norm;
    red_add_f32x4(&g_zero[OFF_AGG1 + (long long)d * HIDC + c * 4], v);
}

// Epilogue 1: self-loop + bias + ELU -> g_h1
__global__ void k_epi1(const float* __restrict__ b1, int N) {
    long long idx = (long long)blockIdx.x * blockDim.x + threadIdx.x;
    if (idx >= (long long)N * 16) return;
    int i = (int)(idx >> 4);
    int c = (int)(idx & 15);
    float di = g_dinv[i];
    float self = di * di;
    long long o = (long long)i * HIDC + c * 4;
    float4 agg = reinterpret_cast<const float4*>(&g_zero[OFF_AGG1 + o])[0];
    float4 xw  = reinterpret_cast<const float4*>(&g_XW[o])[0];
    float4 bb  = reinterpret_cast<const float4*>(&b1[c * 4])[0];
    float4 v;
    v.x = agg.x + xw.x * self + bb.x;
    v.y = agg.y + xw.y * self + bb.y;
    v.z = agg.z + xw.z * self + bb.z;
    v.w = agg.w + xw.w * self + bb.w;
    reinterpret_cast<float4*>(&g_h1[o])[0] = elu4(v);
}

// GEMM2: g_h1[N,64] @ {Wmu,Wsig}[64,64] -> g_T[2][N,64]
// block = 256 threads; t = upper bit selects mu/sig half.
__global__ void k_gemm2(const float* __restrict__ Wmu, const float* __restrict__ Wsig, int N) {
    __shared__ float Ws[2][HIDC * HIDC];
    int t = threadIdx.x >> 7;
    int tid = threadIdx.x & 127;
    const float* W = t ? Wsig : Wmu;
    for (int i = tid; i < HIDC * HIDC / 4; i += 128)
        reinterpret_cast<float4*>(Ws[t])[i] = reinterpret_cast<const float4*>(W)[i];
    __syncthreads();

    const int q  = tid & 15;
    const int rg = tid >> 4;
    const int row0 = blockIdx.x * 32;
    float* out = g_T + (long long)t * N64;

    float4 acc[4];
    int rows[4]; bool valid[4];
#pragma unroll
    for (int rr = 0; rr < 4; rr++) {
        rows[rr] = row0 + rg + 8 * rr;
        valid[rr] = rows[rr] < N;
        acc[rr] = make_float4(0.f, 0.f, 0.f, 0.f);
    }

    for (int k4 = 0; k4 < HIDC / 4; k4++) {
        float4 a[4];
#pragma unroll
        for (int rr = 0; rr < 4; rr++)
            a[rr] = valid[rr]
                ? reinterpret_cast<const float4*>(&g_h1[(long long)rows[rr] * HIDC + k4 * 4])[0]
                : make_float4(0.f, 0.f, 0.f, 0.f);
#pragma unroll
        for (int kk = 0; kk < 4; kk++) {
            float4 w = reinterpret_cast<const float4*>(&Ws[t][(k4 * 4 + kk) * HIDC + q * 4])[0];
#pragma unroll
            for (int rr = 0; rr < 4; rr++) {
                float av = (&a[rr].x)[kk];
                acc[rr].x += av * w.x; acc[rr].y += av * w.y;
                acc[rr].z += av * w.z; acc[rr].w += av * w.w;
            }
        }
    }
#pragma unroll
    for (int rr = 0; rr < 4; rr++)
        if (valid[rr])
            reinterpret_cast<float4*>(&out[(long long)rows[rr] * HIDC + q * 4])[0] = acc[rr];
}

// Layer-2 edge aggregation for mu AND sig: 32 threads/edge (lanes 0-15 mu, 16-31 sig).
__global__ void k_agg2(const int* __restrict__ src, const int* __restrict__ dst, int E) {
    long long idx = (long long)blockIdx.x * blockDim.x + threadIdx.x;
    if (idx >= (long long)E * 32) return;
    int e   = (int)(idx >> 5);
    int sub = (int)(idx & 31);
    int t   = sub >> 4;
    int c   = sub & 15;
    int s = src[e], d = dst[e];
    float norm = g_dinv[s] * g_dinv[d];
    const float* T = g_T + (long long)t * N64;
    float* A = &g_zero[(t ? OFF_A1 : OFF_A0)];
    float4 v = reinterpret_cast<const float4*>(&T[(long long)s * HIDC + c * 4])[0];
    v.x *= norm; v.y *= norm; v.z *= norm; v.w *= norm;
    red_add_f32x4(&A[(long long)d * HIDC + c * 4], v);
}

// Epilogue 2 + mean-pool accumulate: self-loop + bias + ELU, then segment sums.
__global__ void k_epi2pool(const float* __restrict__ bmu, const float* __restrict__ bsig,
                           const int* __restrict__ batch, int N) {
    long long idx = (long long)blockIdx.x * blockDim.x + threadIdx.x;
    if (idx >= (long long)N * 32) return;
    int i   = (int)(idx >> 5);
    int sub = (int)(idx & 31);
    int t   = sub >> 4;
    int c   = sub & 15;
    float di = g_dinv[i];
    float self = di * di;
    long long o = (long long)i * HIDC + c * 4;
    const float* T = g_T + (long long)t * N64;
    const float* A = &g_zero[(t ? OFF_A1 : OFF_A0)];
    const float* b = t ? bsig : bmu;
    float4 agg = reinterpret_cast<const float4*>(&A[o])[0];
    float4 tw  = reinterpret_cast<const float4*>(&T[o])[0];
    float4 bb  = reinterpret_cast<const float4*>(&b[c * 4])[0];
    float4 v;
    v.x = agg.x + tw.x * self + bb.x;
    v.y = agg.y + tw.y * self + bb.y;
    v.z = agg.z + tw.z * self + bb.z;
    v.w = agg.w + tw.w * self + bb.w;
    v = elu4(v);
    int g = batch[i];
    red_add_f32x4(&g_zero[OFF_SUMS + ((long long)(t * 64 + g)) * HIDC + c * 4], v);
    if (sub == 0) red_add_f32(&g_zero[OFF_CNT + g], 1.0f);
}

// Final: divide by counts, write [z_mu ; z_sigma] to d_out.
__global__ void k_final(float* __restrict__ out, int G) {
    int tid = blockIdx.x * blockDim.x + threadIdx.x;
    int total = 2 * G * HIDC;
    if (tid >= total) return;
    int t = tid / (G * HIDC);
    int rem = tid - t * G * HIDC;
    int g = rem >> 6;
    int c = rem & 63;
    float cnt = g_zero[OFF_CNT + g];
    cnt = fmaxf(cnt, 1.0f);
    out[tid] = g_zero[OFF_SUMS + (long long)(t * 64 + g) * HIDC + c] / cnt;
}

// ---------------- launch ----------------
extern "C" void kernel_launch(void* const* d_in, const int* in_sizes, int n_in,
                              void* d_out, int out_size) {
    const float* x     = (const float*)d_in[0];
    const int*   ei    = (const int*)d_in[1];
    const int*   batch = (const int*)d_in[2];

    int N = in_sizes[0] / INDIM;   // 50000
    int E = in_sizes[1] / 2;       // 800000
    int G = out_size / (2 * HIDC); // 64

    // num_graphs may or may not be materialized as a 1-element input.
    int wi = 3;
    if (in_sizes[3] == 1) wi = 4;
    const float* W1   = (const float*)d_in[wi + 0];
    const float* b1   = (const float*)d_in[wi + 1];
    const float* Wmu  = (const float*)d_in[wi + 2];
    const float* bmu  = (const float*)d_in[wi + 3];
    const float* Wsig = (const float*)d_in[wi + 4];
    const float* bsig = (const float*)d_in[wi + 5];
    float* out = (float*)d_out;

    const int* src = ei;
    const int* dst = ei + E;

    long long z4 = ZTOT / 4;
    k_zero<<<(unsigned)((z4 + 255) / 256), 256>>>();
    k_deg<<<(E + 255) / 256, 256>>>(dst, E);
    k_dinv<<<(N + 255) / 256, 256>>>(N);
    k_gemm1<<<(N + 31) / 32, 128>>>(x, W1, N);
    {
        long long tthreads = (long long)E * 16;
        k_agg1<<<(unsigned)((tthreads + 255) / 256), 256>>>(src, dst, E);
    }
    {
        long long tthreads = (long long)N * 16;
        k_epi1<<<(unsigned)((tthreads + 255) / 256), 256>>>(b1, N);
    }
    k_gemm2<<<(N + 31) / 32, 256>>>(Wmu, Wsig, N);
    {
        long long tthreads = (long long)E * 32;
        k_agg2<<<(unsigned)((tthreads + 255) / 256), 256>>>(src, dst, E);
    }
    {
        long long tthreads = (long long)N * 32;
        k_epi2pool<<<(unsigned)((tthreads + 255) / 256), 256>>>(bmu, bsig, batch, N);
    }
    k_final<<<(2 * G * HIDC + 255) / 256, 256>>>(out, G);
}

// round 2
// speedup vs baseline: 1.5083x; 1.5083x over previous
#include <cuda_runtime.h>
#include <cuda_bf16.h>
#include <cstdint>

// Problem constants (dataset-fixed shapes).
static constexpr int NN    = 50000;      // nodes
static constexpr int HIDC  = 64;         // hidden/z dim
static constexpr int INDIM = 128;
static constexpr int N64   = NN * HIDC;  // 3,200,000
static constexpr int ECAP  = 1000000;    // edge capacity (dataset: 800000)
static constexpr int SCAN_BLK = 512;
static constexpr int SCAN_NB  = (NN + SCAN_BLK - 1) / SCAN_BLK;  // 98

// ---- scratch (device globals; no allocations allowed) ----
__device__ int   g_cnt[NN];          // in-degree counts (zeroed each launch)
__device__ int   g_offs[NN + 1];     // CSR offsets
__device__ int   g_cursor[NN];       // fill cursors
__device__ int   g_bsum[SCAN_NB];    // scan partials
__device__ int   g_bscan[SCAN_NB];   // scanned partials
__device__ int   g_srcs[ECAP];       // edge src sorted by dst bucket
__device__ float g_dinv[NN];         // rsqrt(deg+1)
__device__ float g_XW[N64];          // x @ W1
__device__ float g_h1[N64];          // ELU(conv1)
__device__ float g_T[2 * N64];       // interleaved [N,128]: h1@Wmu | h1@Wsig
__device__ float g_sums[2 * 64 * 64];// pooled sums (zeroed)
__device__ float g_cntf[64];         // per-graph node counts (zeroed)

// ---------------- helpers ----------------
__device__ __forceinline__ void red_add_f32x4(float* p, float4 v) {
    asm volatile("red.global.add.v4.f32 [%0], {%1,%2,%3,%4};"
                 :: "l"(p), "f"(v.x), "f"(v.y), "f"(v.z), "f"(v.w) : "memory");
}
__device__ __forceinline__ void red_add_f32(float* p, float v) {
    asm volatile("red.global.add.f32 [%0], %1;" :: "l"(p), "f"(v) : "memory");
}
__device__ __forceinline__ float elu1(float x) { return x > 0.0f ? x : expm1f(x); }
__device__ __forceinline__ float4 elu4(float4 v) {
    v.x = elu1(v.x); v.y = elu1(v.y); v.z = elu1(v.z); v.w = elu1(v.w);
    return v;
}
__device__ __forceinline__ float4 fma4(float4 a, float s, float4 acc) {
    acc.x += a.x * s; acc.y += a.y * s; acc.z += a.z * s; acc.w += a.w * s;
    return acc;
}

// ---------------- kernels ----------------

__global__ void k_zero() {
    int i = blockIdx.x * blockDim.x + threadIdx.x;
    if (i < NN) g_cnt[i] = 0;
    if (i < 2 * 64 * 64) g_sums[i] = 0.f;
    if (i < 64) g_cntf[i] = 0.f;
}

__global__ void k_deg(const int* __restrict__ dst, int E) {
    int e = blockIdx.x * blockDim.x + threadIdx.x;
    if (e < E) atomicAdd(&g_cnt[dst[e]], 1);
}

__global__ void k_dinv(int N) {
    int i = blockIdx.x * blockDim.x + threadIdx.x;
    if (i < N) g_dinv[i] = rsqrtf((float)g_cnt[i] + 1.0f);  // +1 self loop
}

// ---- 3-kernel exclusive scan of g_cnt -> g_offs ----
__global__ void k_scan1(int N) {
    __shared__ int sh[SCAN_BLK];
    int tid = threadIdx.x;
    int i = blockIdx.x * SCAN_BLK + tid;
    int v = (i < N) ? g_cnt[i] : 0;
    sh[tid] = v;
    __syncthreads();
#pragma unroll
    for (int off = 1; off < SCAN_BLK; off <<= 1) {
        int t = (tid >= off) ? sh[tid - off] : 0;
        __syncthreads();
        sh[tid] += t;
        __syncthreads();
    }
    if (i < N) g_offs[i] = sh[tid] - v;              // block-local exclusive
    if (tid == SCAN_BLK - 1) g_bsum[blockIdx.x] = sh[tid];
}

__global__ void k_scan2() {
    if (threadIdx.x == 0 && blockIdx.x == 0) {
        int run = 0;
        for (int b = 0; b < SCAN_NB; b++) { g_bscan[b] = run; run += g_bsum[b]; }
    }
}

__global__ void k_scan3(int N, int E) {
    int i = blockIdx.x * blockDim.x + threadIdx.x;
    if (i < N) {
        int o = g_offs[i] + g_bscan[i / SCAN_BLK];
        g_offs[i] = o;
        g_cursor[i] = o;
    }
    if (i == 0) g_offs[N] = E;
}

__global__ void k_fill(const int* __restrict__ src, const int* __restrict__ dst, int E) {
    int e = blockIdx.x * blockDim.x + threadIdx.x;
    if (e < E) {
        int d = dst[e];
        int pos = atomicAdd(&g_cursor[d], 1);
        g_srcs[pos] = src[e];
    }
}

// GEMM1: X[N,128] @ W[128,64] -> g_XW[N,64]
__global__ void k_gemm1(const float* __restrict__ X, const float* __restrict__ W, int N) {
    __shared__ float Ws[INDIM * HIDC];
    for (int i = threadIdx.x; i < INDIM * HIDC / 4; i += 128)
        reinterpret_cast<float4*>(Ws)[i] = reinterpret_cast<const float4*>(W)[i];
    __syncthreads();

    const int q  = threadIdx.x & 15;
    const int rg = threadIdx.x >> 4;
    const int row0 = blockIdx.x * 32;

    float4 acc[4];
    int rows[4]; bool valid[4];
#pragma unroll
    for (int rr = 0; rr < 4; rr++) {
        rows[rr] = row0 + rg + 8 * rr;
        valid[rr] = rows[rr] < N;
        acc[rr] = make_float4(0.f, 0.f, 0.f, 0.f);
    }

    for (int k4 = 0; k4 < INDIM / 4; k4++) {
        float4 a[4];
#pragma unroll
        for (int rr = 0; rr < 4; rr++)
            a[rr] = valid[rr]
                ? reinterpret_cast<const float4*>(&X[(long long)rows[rr] * INDIM + k4 * 4])[0]
                : make_float4(0.f, 0.f, 0.f, 0.f);
#pragma unroll
        for (int kk = 0; kk < 4; kk++) {
            float4 w = reinterpret_cast<const float4*>(&Ws[(k4 * 4 + kk) * HIDC + q * 4])[0];
#pragma unroll
            for (int rr = 0; rr < 4; rr++) {
                float av = (&a[rr].x)[kk];
                acc[rr] = fma4(w, av, acc[rr]);
            }
        }
    }
#pragma unroll
    for (int rr = 0; rr < 4; rr++)
        if (valid[rr])
            reinterpret_cast<float4*>(&g_XW[(long long)rows[rr] * HIDC + q * 4])[0] = acc[rr];
}

// Layer-1 CSR gather + self-loop + bias + ELU -> g_h1. 16 lanes per node.
__global__ void k_gather1(const float* __restrict__ b1, int N) {
    long long idx = (long long)blockIdx.x * blockDim.x + threadIdx.x;
    if (idx >= (long long)N * 16) return;
    int node = (int)(idx >> 4);
    int c    = (int)(idx & 15);
    float di = g_dinv[node];
    float4 acc = reinterpret_cast<const float4*>(&g_XW[(long long)node * HIDC + c * 4])[0];
    float self = di * di;
    acc.x *= self; acc.y *= self; acc.z *= self; acc.w *= self;

    int beg = g_offs[node], end = g_offs[node + 1];
    if (beg < end) {
        int s = g_srcs[beg];
        for (int k = beg; k < end - 1; k++) {
            int s2 = g_srcs[k + 1];                         // prefetch next src
            float w = g_dinv[s] * di;
            float4 v = reinterpret_cast<const float4*>(&g_XW[(long long)s * HIDC + c * 4])[0];
            acc = fma4(v, w, acc);
            s = s2;
        }
        float w = g_dinv[s] * di;
        float4 v = reinterpret_cast<const float4*>(&g_XW[(long long)s * HIDC + c * 4])[0];
        acc = fma4(v, w, acc);
    }
    float4 bb = reinterpret_cast<const float4*>(&b1[c * 4])[0];
    acc.x += bb.x; acc.y += bb.y; acc.z += bb.z; acc.w += bb.w;
    reinterpret_cast<float4*>(&g_h1[(long long)node * HIDC + c * 4])[0] = elu4(acc);
}

// GEMM2: g_h1[N,64] @ {Wmu,Wsig} -> g_T interleaved [N,128] (mu cols 0-63, sig 64-127)
__global__ void k_gemm2(const float* __restrict__ Wmu, const float* __restrict__ Wsig, int N) {
    __shared__ float Ws[2][HIDC * HIDC];
    int t = threadIdx.x >> 7;
    int tid = threadIdx.x & 127;
    const float* W = t ? Wsig : Wmu;
    for (int i = tid; i < HIDC * HIDC / 4; i += 128)
        reinterpret_cast<float4*>(Ws[t])[i] = reinterpret_cast<const float4*>(W)[i];
    __syncthreads();

    const int q  = tid & 15;
    const int rg = tid >> 4;
    const int row0 = blockIdx.x * 32;

    float4 acc[4];
    int rows[4]; bool valid[4];
#pragma unroll
    for (int rr = 0; rr < 4; rr++) {
        rows[rr] = row0 + rg + 8 * rr;
        valid[rr] = rows[rr] < N;
        acc[rr] = make_float4(0.f, 0.f, 0.f, 0.f);
    }

    for (int k4 = 0; k4 < HIDC / 4; k4++) {
        float4 a[4];
#pragma unroll
        for (int rr = 0; rr < 4; rr++)
            a[rr] = valid[rr]
                ? reinterpret_cast<const float4*>(&g_h1[(long long)rows[rr] * HIDC + k4 * 4])[0]
                : make_float4(0.f, 0.f, 0.f, 0.f);
#pragma unroll
        for (int kk = 0; kk < 4; kk++) {
            float4 w = reinterpret_cast<const float4*>(&Ws[t][(k4 * 4 + kk) * HIDC + q * 4])[0];
#pragma unroll
            for (int rr = 0; rr < 4; rr++) {
                float av = (&a[rr].x)[kk];
                acc[rr] = fma4(w, av, acc[rr]);
            }
        }
    }
#pragma unroll
    for (int rr = 0; rr < 4; rr++)
        if (valid[rr])
            reinterpret_cast<float4*>(&g_T[(long long)rows[rr] * 2 * HIDC + t * HIDC + q * 4])[0] = acc[rr];
}

// Layer-2 CSR gather (mu+sig fused) + self-loop + bias + ELU + mean-pool accumulate.
// 32 lanes per node: lanes 0-15 mu, 16-31 sig; each lane owns one float4 of [N,128].
__global__ void k_gather2(const float* __restrict__ bmu, const float* __restrict__ bsig,
                          const int* __restrict__ batch, int N) {
    long long idx = (long long)blockIdx.x * blockDim.x + threadIdx.x;
    if (idx >= (long long)N * 32) return;
    int node = (int)(idx >> 5);
    int c    = (int)(idx & 31);
    int half = c >> 4;       // 0=mu, 1=sig
    int cc   = c & 15;

    float di = g_dinv[node];
    float4 acc = reinterpret_cast<const float4*>(&g_T[(long long)node * 128 + c * 4])[0];
    float self = di * di;
    acc.x *= self; acc.y *= self; acc.z *= self; acc.w *= self;

    int beg = g_offs[node], end = g_offs[node + 1];
    if (beg < end) {
        int s = g_srcs[beg];
        for (int k = beg; k < end - 1; k++) {
            int s2 = g_srcs[k + 1];
            float w = g_dinv[s] * di;
            float4 v = reinterpret_cast<const float4*>(&g_T[(long long)s * 128 + c * 4])[0];
            acc = fma4(v, w, acc);
            s = s2;
        }
        float w = g_dinv[s] * di;
        float4 v = reinterpret_cast<const float4*>(&g_T[(long long)s * 128 + c * 4])[0];
        acc = fma4(v, w, acc);
    }
    const float* b = half ? bsig : bmu;
    float4 bb = reinterpret_cast<const float4*>(&b[cc * 4])[0];
    acc.x += bb.x; acc.y += bb.y; acc.z += bb.z; acc.w += bb.w;
    acc = elu4(acc);

    int g = batch[node];
    red_add_f32x4(&g_sums[((long long)(half * 64 + g)) * HIDC + cc * 4], acc);
    if (c == 0) red_add_f32(&g_cntf[g], 1.0f);
}

// Final: divide by counts, write [z_mu ; z_sigma] to d_out.
__global__ void k_final(float* __restrict__ out, int G) {
    int tid = blockIdx.x * blockDim.x + threadIdx.x;
    int total = 2 * G * HIDC;
    if (tid >= total) return;
    int t = tid / (G * HIDC);
    int rem = tid - t * G * HIDC;
    int g = rem >> 6;
    int c = rem & 63;
    float cnt = fmaxf(g_cntf[g], 1.0f);
    out[tid] = g_sums[(long long)(t * 64 + g) * HIDC + c] / cnt;
}

// ---------------- launch ----------------
extern "C" void kernel_launch(void* const* d_in, const int* in_sizes, int n_in,
                              void* d_out, int out_size) {
    const float* x     = (const float*)d_in[0];
    const int*   ei    = (const int*)d_in[1];
    const int*   batch = (const int*)d_in[2];

    int N = in_sizes[0] / INDIM;   // 50000
    int E = in_sizes[1] / 2;       // 800000
    int G = out_size / (2 * HIDC); // 64

    int wi = 3;
    if (in_sizes[3] == 1) wi = 4;  // num_graphs may be materialized
    const float* W1   = (const float*)d_in[wi + 0];
    const float* b1   = (const float*)d_in[wi + 1];
    const float* Wmu  = (const float*)d_in[wi + 2];
    const float* bmu  = (const float*)d_in[wi + 3];
    const float* Wsig = (const float*)d_in[wi + 4];
    const float* bsig = (const float*)d_in[wi + 5];
    float* out = (float*)d_out;

    const int* src = ei;
    const int* dst = ei + E;

    k_zero<<<(NN + 255) / 256, 256>>>();
    k_deg<<<(E + 255) / 256, 256>>>(dst, E);
    k_dinv<<<(N + 255) / 256, 256>>>(N);
    k_scan1<<<SCAN_NB, SCAN_BLK>>>(N);
    k_scan2<<<1, 32>>>();
    k_scan3<<<(N + 255) / 256, 256>>>(N, E);
    k_fill<<<(E + 255) / 256, 256>>>(src, dst, E);
    k_gemm1<<<(N + 31) / 32, 128>>>(x, W1, N);
    {
        long long t = (long long)N * 16;
        k_gather1<<<(unsigned)((t + 255) / 256), 256>>>(b1, N);
    }
    k_gemm2<<<(N + 31) / 32, 256>>>(Wmu, Wsig, N);
    {
        long long t = (long long)N * 32;
        k_gather2<<<(unsigned)((t + 255) / 256), 256>>>(bmu, bsig, batch, N);
    }
    k_final<<<(2 * G * HIDC + 255) / 256, 256>>>(out, G);
}

// round 3
// speedup vs baseline: 1.9059x; 1.2636x over previous
#include <cuda_runtime.h>
#include <cuda_bf16.h>
#include <cstdint>

// Problem constants (dataset-fixed shapes).
static constexpr int NN    = 50000;      // nodes
static constexpr int HIDC  = 64;         // hidden/z dim
static constexpr int INDIM = 128;
static constexpr int N64   = NN * HIDC;  // 3,200,000
static constexpr int ECAP  = 1000000;    // edge capacity (dataset: 800000)
static constexpr int SCAN_BLK = 512;
static constexpr int SCAN_NB  = (NN + SCAN_BLK - 1) / SCAN_BLK;  // 98

// ---- scratch (device globals; no allocations allowed) ----
__device__ int   g_cnt[NN];          // in-degree counts (zeroed each launch)
__device__ int   g_offs[NN + 1];     // CSR offsets
__device__ int   g_cursor[NN];       // fill cursors
__device__ int   g_bsum[SCAN_NB];    // scan partials
__device__ int   g_bscan[SCAN_NB];   // scanned partials
__device__ int   g_srcs[ECAP];       // edge src sorted by dst bucket
__device__ float g_dinv[NN];         // rsqrt(deg+1)
__device__ float g_XW[N64];          // x @ W1
__device__ float g_h1[N64];          // ELU(conv1)
__device__ float g_aggh[N64];        // layer-2 aggregated h1 (pre-GEMM)
__device__ float g_sums[2 * 64 * 64];// pooled sums (zeroed)
__device__ float g_cntf[64];         // per-graph node counts (zeroed)

// ---------------- helpers ----------------
__device__ __forceinline__ void red_add_f32x4(float* p, float4 v) {
    asm volatile("red.global.add.v4.f32 [%0], {%1,%2,%3,%4};"
                 :: "l"(p), "f"(v.x), "f"(v.y), "f"(v.z), "f"(v.w) : "memory");
}
__device__ __forceinline__ void red_add_f32(float* p, float v) {
    asm volatile("red.global.add.f32 [%0], %1;" :: "l"(p), "f"(v) : "memory");
}
__device__ __forceinline__ float elu1(float x) { return x > 0.0f ? x : expm1f(x); }
__device__ __forceinline__ float4 elu4(float4 v) {
    v.x = elu1(v.x); v.y = elu1(v.y); v.z = elu1(v.z); v.w = elu1(v.w);
    return v;
}
__device__ __forceinline__ float4 fma4(float4 a, float s, float4 acc) {
    acc.x += a.x * s; acc.y += a.y * s; acc.z += a.z * s; acc.w += a.w * s;
    return acc;
}

// ---------------- kernels ----------------

__global__ void k_zero() {
    int i = blockIdx.x * blockDim.x + threadIdx.x;
    if (i < NN) g_cnt[i] = 0;
    if (i < 2 * 64 * 64) g_sums[i] = 0.f;
    if (i < 64) g_cntf[i] = 0.f;
}

__global__ void k_deg(const int* __restrict__ dst, int E) {
    int e = blockIdx.x * blockDim.x + threadIdx.x;
    if (e < E) atomicAdd(&g_cnt[dst[e]], 1);
}

// ---- exclusive scan of g_cnt -> g_offs ; also computes dinv ----
__global__ void k_scan1(int N) {
    __shared__ int sh[SCAN_BLK];
    int tid = threadIdx.x;
    int i = blockIdx.x * SCAN_BLK + tid;
    int v = (i < N) ? g_cnt[i] : 0;
    if (i < N) g_dinv[i] = rsqrtf((float)v + 1.0f);  // +1 self loop
    sh[tid] = v;
    __syncthreads();
#pragma unroll
    for (int off = 1; off < SCAN_BLK; off <<= 1) {
        int t = (tid >= off) ? sh[tid - off] : 0;
        __syncthreads();
        sh[tid] += t;
        __syncthreads();
    }
    if (i < N) g_offs[i] = sh[tid] - v;              // block-local exclusive
    if (tid == SCAN_BLK - 1) g_bsum[blockIdx.x] = sh[tid];
}

__global__ void k_scan2() {
    if (threadIdx.x == 0 && blockIdx.x == 0) {
        int run = 0;
        for (int b = 0; b < SCAN_NB; b++) { g_bscan[b] = run; run += g_bsum[b]; }
    }
}

__global__ void k_scan3(int N, int E) {
    int i = blockIdx.x * blockDim.x + threadIdx.x;
    if (i < N) {
        int o = g_offs[i] + g_bscan[i / SCAN_BLK];
        g_offs[i] = o;
        g_cursor[i] = o;
    }
    if (i == 0) g_offs[N] = E;
}

__global__ void k_fill(const int* __restrict__ src, const int* __restrict__ dst, int E) {
    int e = blockIdx.x * blockDim.x + threadIdx.x;
    if (e < E) {
        int d = dst[e];
        int pos = atomicAdd(&g_cursor[d], 1);
        g_srcs[pos] = src[e];
    }
}

// GEMM1: X[N,128] @ W[128,64] -> g_XW[N,64]. Double-buffered X loads.
__global__ void k_gemm1(const float* __restrict__ X, const float* __restrict__ W, int N) {
    __shared__ float Ws[INDIM * HIDC];
    for (int i = threadIdx.x; i < INDIM * HIDC / 4; i += 128)
        reinterpret_cast<float4*>(Ws)[i] = reinterpret_cast<const float4*>(W)[i];
    __syncthreads();

    const int q  = threadIdx.x & 15;
    const int rg = threadIdx.x >> 4;
    const int row0 = blockIdx.x * 32;

    float4 acc[4];
    int rows[4]; bool valid[4];
#pragma unroll
    for (int rr = 0; rr < 4; rr++) {
        rows[rr] = row0 + rg + 8 * rr;
        valid[rr] = rows[rr] < N;
        acc[rr] = make_float4(0.f, 0.f, 0.f, 0.f);
    }

    float4 a[4], an[4];
#pragma unroll
    for (int rr = 0; rr < 4; rr++)
        a[rr] = valid[rr]
            ? reinterpret_cast<const float4*>(&X[(long long)rows[rr] * INDIM])[0]
            : make_float4(0.f, 0.f, 0.f, 0.f);

    for (int k4 = 0; k4 < INDIM / 4; k4++) {
        if (k4 + 1 < INDIM / 4) {
#pragma unroll
            for (int rr = 0; rr < 4; rr++)
                an[rr] = valid[rr]
                    ? reinterpret_cast<const float4*>(&X[(long long)rows[rr] * INDIM + (k4 + 1) * 4])[0]
                    : make_float4(0.f, 0.f, 0.f, 0.f);
        }
#pragma unroll
        for (int kk = 0; kk < 4; kk++) {
            float4 w = reinterpret_cast<const float4*>(&Ws[(k4 * 4 + kk) * HIDC + q * 4])[0];
#pragma unroll
            for (int rr = 0; rr < 4; rr++) {
                float av = (&a[rr].x)[kk];
                acc[rr] = fma4(w, av, acc[rr]);
            }
        }
#pragma unroll
        for (int rr = 0; rr < 4; rr++) a[rr] = an[rr];
    }
#pragma unroll
    for (int rr = 0; rr < 4; rr++)
        if (valid[rr])
            reinterpret_cast<float4*>(&g_XW[(long long)rows[rr] * HIDC + q * 4])[0] = acc[rr];
}

// Layer-1 CSR gather + self-loop + bias + ELU -> g_h1. 16 lanes per node.
__global__ void k_gather1(const float* __restrict__ b1, int N) {
    long long idx = (long long)blockIdx.x * blockDim.x + threadIdx.x;
    if (idx >= (long long)N * 16) return;
    int node = (int)(idx >> 4);
    int c    = (int)(idx & 15);
    float di = g_dinv[node];
    float4 acc = reinterpret_cast<const float4*>(&g_XW[(long long)node * HIDC + c * 4])[0];
    float self = di * di;
    acc.x *= self; acc.y *= self; acc.z *= self; acc.w *= self;

    int beg = g_offs[node], end = g_offs[node + 1];
    if (beg < end) {
        int s = g_srcs[beg];
        for (int k = beg; k < end - 1; k++) {
            int s2 = g_srcs[k + 1];                         // prefetch next src
            float w = g_dinv[s] * di;
            float4 v = reinterpret_cast<const float4*>(&g_XW[(long long)s * HIDC + c * 4])[0];
            acc = fma4(v, w, acc);
            s = s2;
        }
        float w = g_dinv[s] * di;
        float4 v = reinterpret_cast<const float4*>(&g_XW[(long long)s * HIDC + c * 4])[0];
        acc = fma4(v, w, acc);
    }
    float4 bb = reinterpret_cast<const float4*>(&b1[c * 4])[0];
    acc.x += bb.x; acc.y += bb.y; acc.z += bb.z; acc.w += bb.w;
    reinterpret_cast<float4*>(&g_h1[(long long)node * HIDC + c * 4])[0] = elu4(acc);
}

// Layer-2 CSR gather (pre-GEMM, by linearity): aggh = self*h1 + sum norm*h1[s].
__global__ void k_gather2(int N) {
    long long idx = (long long)blockIdx.x * blockDim.x + threadIdx.x;
    if (idx >= (long long)N * 16) return;
    int node = (int)(idx >> 4);
    int c    = (int)(idx & 15);
    float di = g_dinv[node];
    float4 acc = reinterpret_cast<const float4*>(&g_h1[(long long)node * HIDC + c * 4])[0];
    float self = di * di;
    acc.x *= self; acc.y *= self; acc.z *= self; acc.w *= self;

    int beg = g_offs[node], end = g_offs[node + 1];
    if (beg < end) {
        int s = g_srcs[beg];
        for (int k = beg; k < end - 1; k++) {
            int s2 = g_srcs[k + 1];
            float w = g_dinv[s] * di;
            float4 v = reinterpret_cast<const float4*>(&g_h1[(long long)s * HIDC + c * 4])[0];
            acc = fma4(v, w, acc);
            s = s2;
        }
        float w = g_dinv[s] * di;
        float4 v = reinterpret_cast<const float4*>(&g_h1[(long long)s * HIDC + c * 4])[0];
        acc = fma4(v, w, acc);
    }
    reinterpret_cast<float4*>(&g_aggh[(long long)node * HIDC + c * 4])[0] = acc;
}

// Fused: z = aggh @ {Wmu,Wsig} + bias, ELU, mean-pool accumulate.
// Block = 128 threads, 32 rows. Thread (q 0..15, rg 0..7): 4 rows x 4 cols x {mu,sig}.
__global__ void k_gemm2pool(const float* __restrict__ Wmu, const float* __restrict__ bmu,
                            const float* __restrict__ Wsig, const float* __restrict__ bsig,
                            const int* __restrict__ batch, int N) {
    __shared__ float Wms[HIDC * HIDC];
    __shared__ float Wss[HIDC * HIDC];
    __shared__ float spool[128];  // 64 mu + 64 sig
    for (int i = threadIdx.x; i < HIDC * HIDC / 4; i += 128) {
        reinterpret_cast<float4*>(Wms)[i] = reinterpret_cast<const float4*>(Wmu)[i];
        reinterpret_cast<float4*>(Wss)[i] = reinterpret_cast<const float4*>(Wsig)[i];
    }
    if (threadIdx.x < 128) spool[threadIdx.x] = 0.f;
    __syncthreads();

    const int q  = threadIdx.x & 15;
    const int rg = threadIdx.x >> 4;
    const int row0 = blockIdx.x * 32;

    float4 am[4], as4[4];
    int rows[4]; bool valid[4];
#pragma unroll
    for (int rr = 0; rr < 4; rr++) {
        rows[rr] = row0 + rg + 8 * rr;
        valid[rr] = rows[rr] < N;
        am[rr] = make_float4(0.f, 0.f, 0.f, 0.f);
        as4[rr] = make_float4(0.f, 0.f, 0.f, 0.f);
    }

    for (int k4 = 0; k4 < HIDC / 4; k4++) {
        float4 a[4];
#pragma unroll
        for (int rr = 0; rr < 4; rr++)
            a[rr] = valid[rr]
                ? reinterpret_cast<const float4*>(&g_aggh[(long long)rows[rr] * HIDC + k4 * 4])[0]
                : make_float4(0.f, 0.f, 0.f, 0.f);
#pragma unroll
        for (int kk = 0; kk < 4; kk++) {
            float4 wm = reinterpret_cast<const float4*>(&Wms[(k4 * 4 + kk) * HIDC + q * 4])[0];
            float4 ws = reinterpret_cast<const float4*>(&Wss[(k4 * 4 + kk) * HIDC + q * 4])[0];
#pragma unroll
            for (int rr = 0; rr < 4; rr++) {
                float av = (&a[rr].x)[kk];
                am[rr]  = fma4(wm, av, am[rr]);
                as4[rr] = fma4(ws, av, as4[rr]);
            }
        }
    }

    float4 bbm = reinterpret_cast<const float4*>(&bmu[q * 4])[0];
    float4 bbs = reinterpret_cast<const float4*>(&bsig[q * 4])[0];
#pragma unroll
    for (int rr = 0; rr < 4; rr++) {
        am[rr].x += bbm.x; am[rr].y += bbm.y; am[rr].z += bbm.z; am[rr].w += bbm.w;
        as4[rr].x += bbs.x; as4[rr].y += bbs.y; as4[rr].z += bbs.z; as4[rr].w += bbs.w;
        am[rr]  = elu4(am[rr]);
        as4[rr] = elu4(as4[rr]);
    }

    int lastRow = min(row0 + 31, N - 1);
    int g0 = batch[row0];
    int g1 = batch[lastRow];

    if (g0 == g1) {
        // Fast path: whole block is one graph. Pre-sum rows locally, reduce in smem.
        float4 sm = make_float4(0.f, 0.f, 0.f, 0.f);
        float4 ss = make_float4(0.f, 0.f, 0.f, 0.f);
        int nv = 0;
#pragma unroll
        for (int rr = 0; rr < 4; rr++) {
            if (valid[rr]) {
                sm.x += am[rr].x; sm.y += am[rr].y; sm.z += am[rr].z; sm.w += am[rr].w;
                ss.x += as4[rr].x; ss.y += as4[rr].y; ss.z += as4[rr].z; ss.w += as4[rr].w;
                nv++;
            }
        }
        atomicAdd(&spool[q * 4 + 0], sm.x);
        atomicAdd(&spool[q * 4 + 1], sm.y);
        atomicAdd(&spool[q * 4 + 2], sm.z);
        atomicAdd(&spool[q * 4 + 3], sm.w);
        atomicAdd(&spool[64 + q * 4 + 0], ss.x);
        atomicAdd(&spool[64 + q * 4 + 1], ss.y);
        atomicAdd(&spool[64 + q * 4 + 2], ss.z);
        atomicAdd(&spool[64 + q * 4 + 3], ss.w);
        __syncthreads();
        if (threadIdx.x < 32) {
            int half = threadIdx.x >> 4;   // 0=mu, 1=sig
            int cc   = threadIdx.x & 15;
            float4 v = reinterpret_cast<const float4*>(&spool[half * 64 + cc * 4])[0];
            red_add_f32x4(&g_sums[(long long)(half * 64 + g0) * HIDC + cc * 4], v);
        }
        if (threadIdx.x == 0) {
            int cnt = min(N - row0, 32);
            red_add_f32(&g_cntf[g0], (float)cnt);
        }
    } else {
        // Slow path: rows span graphs; per-row atomics.
#pragma unroll
        for (int rr = 0; rr < 4; rr++) {
            if (!valid[rr]) continue;
            int g = batch[rows[rr]];
            red_add_f32x4(&g_sums[(long long)(0 * 64 + g) * HIDC + q * 4], am[rr]);
            red_add_f32x4(&g_sums[(long long)(1 * 64 + g) * HIDC + q * 4], as4[rr]);
            if (q == 0) red_add_f32(&g_cntf[g], 1.0f);
        }
    }
}

// Final: divide by counts, write [z_mu ; z_sigma] to d_out.
__global__ void k_final(float* __restrict__ out, int G) {
    int tid = blockIdx.x * blockDim.x + threadIdx.x;
    int total = 2 * G * HIDC;
    if (tid >= total) return;
    int t = tid / (G * HIDC);
    int rem = tid - t * G * HIDC;
    int g = rem >> 6;
    int c = rem & 63;
    float cnt = fmaxf(g_cntf[g], 1.0f);
    out[tid] = g_sums[(long long)(t * 64 + g) * HIDC + c] / cnt;
}

// ---------------- launch ----------------
extern "C" void kernel_launch(void* const* d_in, const int* in_sizes, int n_in,
                              void* d_out, int out_size) {
    const float* x     = (const float*)d_in[0];
    const int*   ei    = (const int*)d_in[1];
    const int*   batch = (const int*)d_in[2];

    int N = in_sizes[0] / INDIM;   // 50000
    int E = in_sizes[1] / 2;       // 800000
    int G = out_size / (2 * HIDC); // 64

    int wi = 3;
    if (in_sizes[3] == 1) wi = 4;  // num_graphs may be materialized
    const float* W1   = (const float*)d_in[wi + 0];
    const float* b1   = (const float*)d_in[wi + 1];
    const float* Wmu  = (const float*)d_in[wi + 2];
    const float* bmu  = (const float*)d_in[wi + 3];
    const float* Wsig = (const float*)d_in[wi + 4];
    const float* bsig = (const float*)d_in[wi + 5];
    float* out = (float*)d_out;

    const int* src = ei;
    const int* dst = ei + E;

    k_zero<<<(NN + 255) / 256, 256>>>();
    k_deg<<<(E + 255) / 256, 256>>>(dst, E);
    k_scan1<<<SCAN_NB, SCAN_BLK>>>(N);
    k_scan2<<<1, 32>>>();
    k_scan3<<<(N + 255) / 256, 256>>>(N, E);
    k_fill<<<(E + 255) / 256, 256>>>(src, dst, E);
    k_gemm1<<<(N + 31) / 32, 128>>>(x, W1, N);
    {
        long long t = (long long)N * 16;
        k_gather1<<<(unsigned)((t + 255) / 256), 256>>>(b1, N);
    }
    {
        long long t = (long long)N * 16;
        k_gather2<<<(unsigned)((t + 255) / 256), 256>>>(N);
    }
    k_gemm2pool<<<(N + 31) / 32, 128>>>(Wmu, bmu, Wsig, bsig, batch, N);
    k_final<<<(2 * G * HIDC + 255) / 256, 256>>>(out, G);
}

// round 4
// speedup vs baseline: 2.0617x; 1.0818x over previous
#include <cuda_runtime.h>
#include <cuda_bf16.h>
#include <cstdint>

// Problem constants (dataset-fixed shapes).
static constexpr int NN    = 50000;      // nodes
static constexpr int HIDC  = 64;         // hidden/z dim
static constexpr int INDIM = 128;
static constexpr int N64   = NN * HIDC;  // 3,200,000
static constexpr int ECAP  = 1000000;    // edge capacity (dataset: 800000)
static constexpr int SCAN_BLK = 512;
static constexpr int SCAN_NB  = (NN + SCAN_BLK - 1) / SCAN_BLK;  // 98

// ---- scratch (device globals; no allocations allowed) ----
__device__ int   g_cnt[NN];
__device__ int   g_offs[NN + 1];
__device__ int   g_cursor[NN];
__device__ int   g_bsum[SCAN_NB];
__device__ int   g_srcs[ECAP];
__device__ float g_dinv[NN];
__device__ float g_XW[N64];
__device__ float g_h1[N64];
__device__ float g_sums[2 * 64 * 64];
__device__ float g_cntf[64];

// ---------------- helpers ----------------
__device__ __forceinline__ void red_add_f32x4(float* p, float4 v) {
    asm volatile("red.global.add.v4.f32 [%0], {%1,%2,%3,%4};"
                 :: "l"(p), "f"(v.x), "f"(v.y), "f"(v.z), "f"(v.w) : "memory");
}
__device__ __forceinline__ void red_add_f32(float* p, float v) {
    asm volatile("red.global.add.f32 [%0], %1;" :: "l"(p), "f"(v) : "memory");
}
__device__ __forceinline__ float elu1(float x) { return x > 0.0f ? x : expm1f(x); }
__device__ __forceinline__ float4 elu4(float4 v) {
    v.x = elu1(v.x); v.y = elu1(v.y); v.z = elu1(v.z); v.w = elu1(v.w);
    return v;
}
__device__ __forceinline__ float4 fma4(float4 a, float s, float4 acc) {
    acc.x += a.x * s; acc.y += a.y * s; acc.z += a.z * s; acc.w += a.w * s;
    return acc;
}
__device__ __forceinline__ float4 add4(float4 a, float4 b) {
    a.x += b.x; a.y += b.y; a.z += b.z; a.w += b.w; return a;
}

// CSR gather of one (node, float4-slice): acc starts with self-loop term.
// Unrolled x4 for MLP.
__device__ __forceinline__ float4 csr_gather(const float* __restrict__ F,
                                             int node, int c, float di, float4 acc0) {
    int beg = g_offs[node], end = g_offs[node + 1];
    float4 z = make_float4(0.f, 0.f, 0.f, 0.f);
    float4 acc1 = z, acc2 = z, acc3 = z;
    int k = beg;
    for (; k + 4 <= end; k += 4) {
        int s0 = g_srcs[k + 0], s1 = g_srcs[k + 1];
        int s2 = g_srcs[k + 2], s3 = g_srcs[k + 3];
        float w0 = g_dinv[s0] * di, w1 = g_dinv[s1] * di;
        float w2 = g_dinv[s2] * di, w3 = g_dinv[s3] * di;
        float4 v0 = reinterpret_cast<const float4*>(&F[(long long)s0 * HIDC + c * 4])[0];
        float4 v1 = reinterpret_cast<const float4*>(&F[(long long)s1 * HIDC + c * 4])[0];
        float4 v2 = reinterpret_cast<const float4*>(&F[(long long)s2 * HIDC + c * 4])[0];
        float4 v3 = reinterpret_cast<const float4*>(&F[(long long)s3 * HIDC + c * 4])[0];
        acc0 = fma4(v0, w0, acc0);
        acc1 = fma4(v1, w1, acc1);
        acc2 = fma4(v2, w2, acc2);
        acc3 = fma4(v3, w3, acc3);
    }
    for (; k < end; k++) {
        int s = g_srcs[k];
        float w = g_dinv[s] * di;
        float4 v = reinterpret_cast<const float4*>(&F[(long long)s * HIDC + c * 4])[0];
        acc0 = fma4(v, w, acc0);
    }
    return add4(add4(acc0, acc1), add4(acc2, acc3));
}

// ---------------- kernels ----------------

__global__ void k_zero() {
    int i = blockIdx.x * blockDim.x + threadIdx.x;
    if (i < NN) g_cnt[i] = 0;
    if (i < 2 * 64 * 64) g_sums[i] = 0.f;
    if (i < 64) g_cntf[i] = 0.f;
}

__global__ void k_deg(const int* __restrict__ dst, int E) {
    int e = blockIdx.x * blockDim.x + threadIdx.x;
    if (e < E) atomicAdd(&g_cnt[dst[e]], 1);
}

// block-local exclusive scan of counts; also dinv and per-block sums.
__global__ void k_scan1(int N) {
    __shared__ int sh[SCAN_BLK];
    int tid = threadIdx.x;
    int i = blockIdx.x * SCAN_BLK + tid;
    int v = (i < N) ? g_cnt[i] : 0;
    if (i < N) g_dinv[i] = rsqrtf((float)v + 1.0f);  // +1 self loop
    sh[tid] = v;
    __syncthreads();
#pragma unroll
    for (int off = 1; off < SCAN_BLK; off <<= 1) {
        int t = (tid >= off) ? sh[tid - off] : 0;
        __syncthreads();
        sh[tid] += t;
        __syncthreads();
    }
    if (i < N) g_offs[i] = sh[tid] - v;
    if (tid == SCAN_BLK - 1) g_bsum[blockIdx.x] = sh[tid];
}

// Adds cross-block prefix (computed in-block from the 98 partials) -> offsets+cursors.
__global__ void k_scan3(int N, int E) {
    __shared__ int sb[SCAN_NB];
    for (int t = threadIdx.x; t < SCAN_NB; t += blockDim.x) sb[t] = g_bsum[t];
    __syncthreads();
    int i = blockIdx.x * blockDim.x + threadIdx.x;
    if (i < N) {
        int blk = i / SCAN_BLK;
        int base = 0;
        for (int b = 0; b < blk; b++) base += sb[b];  // broadcast smem reads
        int o = g_offs[i] + base;
        g_offs[i] = o;
        g_cursor[i] = o;
    }
    if (i == 0) g_offs[N] = E;
}

__global__ void k_fill(const int* __restrict__ src, const int* __restrict__ dst, int E) {
    int e = blockIdx.x * blockDim.x + threadIdx.x;
    if (e < E) {
        int d = dst[e];
        int pos = atomicAdd(&g_cursor[d], 1);
        g_srcs[pos] = src[e];
    }
}

// GEMM1: X[N,128] @ W[128,64] -> g_XW. 64 rows/block, 128 threads, 8 rows/thread.
__global__ __launch_bounds__(128) void k_gemm1(const float* __restrict__ X,
                                               const float* __restrict__ W, int N) {
    __shared__ float Ws[INDIM * HIDC];
    for (int i = threadIdx.x; i < INDIM * HIDC / 4; i += 128)
        reinterpret_cast<float4*>(Ws)[i] = reinterpret_cast<const float4*>(W)[i];
    __syncthreads();

    const int q  = threadIdx.x & 15;
    const int rg = threadIdx.x >> 4;
    const int row0 = blockIdx.x * 64;

    float4 acc[8];
    int rows[8]; bool valid[8];
#pragma unroll
    for (int rr = 0; rr < 8; rr++) {
        rows[rr] = row0 + rg + 8 * rr;
        valid[rr] = rows[rr] < N;
        acc[rr] = make_float4(0.f, 0.f, 0.f, 0.f);
    }

    for (int k4 = 0; k4 < INDIM / 4; k4++) {
        float4 a[8];
#pragma unroll
        for (int rr = 0; rr < 8; rr++)
            a[rr] = valid[rr]
                ? reinterpret_cast<const float4*>(&X[(long long)rows[rr] * INDIM + k4 * 4])[0]
                : make_float4(0.f, 0.f, 0.f, 0.f);
#pragma unroll
        for (int kk = 0; kk < 4; kk++) {
            float4 w = reinterpret_cast<const float4*>(&Ws[(k4 * 4 + kk) * HIDC + q * 4])[0];
#pragma unroll
            for (int rr = 0; rr < 8; rr++) {
                float av = (&a[rr].x)[kk];
                acc[rr] = fma4(w, av, acc[rr]);
            }
        }
    }
#pragma unroll
    for (int rr = 0; rr < 8; rr++)
        if (valid[rr])
            reinterpret_cast<float4*>(&g_XW[(long long)rows[rr] * HIDC + q * 4])[0] = acc[rr];
}

// Layer-1 CSR gather + self-loop + bias + ELU -> g_h1. 16 lanes per node.
__global__ void k_gather1(const float* __restrict__ b1, int N) {
    long long idx = (long long)blockIdx.x * blockDim.x + threadIdx.x;
    if (idx >= (long long)N * 16) return;
    int node = (int)(idx >> 4);
    int c    = (int)(idx & 15);
    float di = g_dinv[node];
    float4 acc = reinterpret_cast<const float4*>(&g_XW[(long long)node * HIDC + c * 4])[0];
    float self = di * di;
    acc.x *= self; acc.y *= self; acc.z *= self; acc.w *= self;

    acc = csr_gather(g_XW, node, c, di, acc);

    float4 bb = reinterpret_cast<const float4*>(&b1[c * 4])[0];
    acc.x += bb.x; acc.y += bb.y; acc.z += bb.z; acc.w += bb.w;
    reinterpret_cast<float4*>(&g_h1[(long long)node * HIDC + c * 4])[0] = elu4(acc);
}

// Fused layer-2: CSR gather h1 into smem tile (64 nodes), then
// z = tile @ {Wmu,Wsig} + bias, ELU, mean-pool accumulate.
// 256 threads/block.
__global__ __launch_bounds__(256) void k_gather2gemm2pool(
        const float* __restrict__ Wmu, const float* __restrict__ bmu,
        const float* __restrict__ Wsig, const float* __restrict__ bsig,
        const int* __restrict__ batch, int N) {
    __shared__ float Wms[HIDC * HIDC];
    __shared__ float Wss[HIDC * HIDC];
    __shared__ float tile[64 * HIDC];   // 16 KB
    __shared__ float spool[128];        // 64 mu + 64 sig

    for (int i = threadIdx.x; i < HIDC * HIDC / 4; i += 256) {
        reinterpret_cast<float4*>(Wms)[i] = reinterpret_cast<const float4*>(Wmu)[i];
        reinterpret_cast<float4*>(Wss)[i] = reinterpret_cast<const float4*>(Wsig)[i];
    }
    if (threadIdx.x < 128) spool[threadIdx.x] = 0.f;

    const int row0 = blockIdx.x * 64;

    // ---- Phase A: gather 64 nodes into smem tile ----
    {
        int c  = threadIdx.x & 15;     // float4 column
        int ng = threadIdx.x >> 4;     // 0..15
#pragma unroll
        for (int pp = 0; pp < 4; pp++) {
            int ln = ng + 16 * pp;     // local node 0..63
            int node = row0 + ln;
            float4 acc;
            if (node < N) {
                float di = g_dinv[node];
                acc = reinterpret_cast<const float4*>(&g_h1[(long long)node * HIDC + c * 4])[0];
                float self = di * di;
                acc.x *= self; acc.y *= self; acc.z *= self; acc.w *= self;
                acc = csr_gather(g_h1, node, c, di, acc);
            } else {
                acc = make_float4(0.f, 0.f, 0.f, 0.f);
            }
            reinterpret_cast<float4*>(&tile[ln * HIDC + c * 4])[0] = acc;
        }
    }
    __syncthreads();

    // ---- Phase B: dual GEMM from smem + bias + ELU + pool ----
    const int q  = threadIdx.x & 15;
    const int rg = threadIdx.x >> 4;   // 0..15

    float4 am[4], as4[4];
    int rows[4]; bool valid[4];
#pragma unroll
    for (int rr = 0; rr < 4; rr++) {
        rows[rr] = row0 + rg + 16 * rr;
        valid[rr] = rows[rr] < N;
        am[rr]  = make_float4(0.f, 0.f, 0.f, 0.f);
        as4[rr] = make_float4(0.f, 0.f, 0.f, 0.f);
    }

    for (int k4 = 0; k4 < HIDC / 4; k4++) {
        float4 a[4];
#pragma unroll
        for (int rr = 0; rr < 4; rr++)
            a[rr] = reinterpret_cast<const float4*>(&tile[(rg + 16 * rr) * HIDC + k4 * 4])[0];
#pragma unroll
        for (int kk = 0; kk < 4; kk++) {
            float4 wm = reinterpret_cast<const float4*>(&Wms[(k4 * 4 + kk) * HIDC + q * 4])[0];
            float4 ws = reinterpret_cast<const float4*>(&Wss[(k4 * 4 + kk) * HIDC + q * 4])[0];
#pragma unroll
            for (int rr = 0; rr < 4; rr++) {
                float av = (&a[rr].x)[kk];
                am[rr]  = fma4(wm, av, am[rr]);
                as4[rr] = fma4(ws, av, as4[rr]);
            }
        }
    }

    float4 bbm = reinterpret_cast<const float4*>(&bmu[q * 4])[0];
    float4 bbs = reinterpret_cast<const float4*>(&bsig[q * 4])[0];
#pragma unroll
    for (int rr = 0; rr < 4; rr++) {
        am[rr]  = elu4(add4(am[rr], bbm));
        as4[rr] = elu4(add4(as4[rr], bbs));
    }

    int lastRow = min(row0 + 63, N - 1);
    int g0 = batch[row0];
    int g1 = batch[lastRow];

    if (g0 == g1) {
        float4 sm = make_float4(0.f, 0.f, 0.f, 0.f);
        float4 ss = make_float4(0.f, 0.f, 0.f, 0.f);
#pragma unroll
        for (int rr = 0; rr < 4; rr++) {
            if (valid[rr]) { sm = add4(sm, am[rr]); ss = add4(ss, as4[rr]); }
        }
        atomicAdd(&spool[q * 4 + 0], sm.x);
        atomicAdd(&spool[q * 4 + 1], sm.y);
        atomicAdd(&spool[q * 4 + 2], sm.z);
        atomicAdd(&spool[q * 4 + 3], sm.w);
        atomicAdd(&spool[64 + q * 4 + 0], ss.x);
        atomicAdd(&spool[64 + q * 4 + 1], ss.y);
        atomicAdd(&spool[64 + q * 4 + 2], ss.z);
        atomicAdd(&spool[64 + q * 4 + 3], ss.w);
        __syncthreads();
        if (threadIdx.x < 32) {
            int half = threadIdx.x >> 4;
            int cc   = threadIdx.x & 15;
            float4 v = reinterpret_cast<const float4*>(&spool[half * 64 + cc * 4])[0];
            red_add_f32x4(&g_sums[(long long)(half * 64 + g0) * HIDC + cc * 4], v);
        }
        if (threadIdx.x == 0) {
            int cnt = min(N - row0, 64);
            red_add_f32(&g_cntf[g0], (float)cnt);
        }
    } else {
#pragma unroll
        for (int rr = 0; rr < 4; rr++) {
            if (!valid[rr]) continue;
            int g = batch[rows[rr]];
            red_add_f32x4(&g_sums[(long long)(0 * 64 + g) * HIDC + q * 4], am[rr]);
            red_add_f32x4(&g_sums[(long long)(1 * 64 + g) * HIDC + q * 4], as4[rr]);
            if (q == 0) red_add_f32(&g_cntf[g], 1.0f);
        }
    }
}

// Final: divide by counts, write [z_mu ; z_sigma] to d_out.
__global__ void k_final(float* __restrict__ out, int G) {
    int tid = blockIdx.x * blockDim.x + threadIdx.x;
    int total = 2 * G * HIDC;
    if (tid >= total) return;
    int t = tid / (G * HIDC);
    int rem = tid - t * G * HIDC;
    int g = rem >> 6;
    int c = rem & 63;
    float cnt = fmaxf(g_cntf[g], 1.0f);
    out[tid] = g_sums[(long long)(t * 64 + g) * HIDC + c] / cnt;
}

// ---------------- launch ----------------
extern "C" void kernel_launch(void* const* d_in, const int* in_sizes, int n_in,
                              void* d_out, int out_size) {
    const float* x     = (const float*)d_in[0];
    const int*   ei    = (const int*)d_in[1];
    const int*   batch = (const int*)d_in[2];

    int N = in_sizes[0] / INDIM;   // 50000
    int E = in_sizes[1] / 2;       // 800000
    int G = out_size / (2 * HIDC); // 64

    int wi = 3;
    if (in_sizes[3] == 1) wi = 4;  // num_graphs may be materialized
    const float* W1   = (const float*)d_in[wi + 0];
    const float* b1   = (const float*)d_in[wi + 1];
    const float* Wmu  = (const float*)d_in[wi + 2];
    const float* bmu  = (const float*)d_in[wi + 3];
    const float* Wsig = (const float*)d_in[wi + 4];
    const float* bsig = (const float*)d_in[wi + 5];
    float* out = (float*)d_out;

    const int* src = ei;
    const int* dst = ei + E;

    k_zero<<<(NN + 255) / 256, 256>>>();
    k_deg<<<(E + 255) / 256, 256>>>(dst, E);
    k_scan1<<<SCAN_NB, SCAN_BLK>>>(N);
    k_scan3<<<(N + 255) / 256, 256>>>(N, E);
    k_fill<<<(E + 255) / 256, 256>>>(src, dst, E);
    k_gemm1<<<(N + 63) / 64, 128>>>(x, W1, N);
    {
        long long t = (long long)N * 16;
        k_gather1<<<(unsigned)((t + 255) / 256), 256>>>(b1, N);
    }
    k_gather2gemm2pool<<<(N + 63) / 64, 256>>>(Wmu, bmu, Wsig, bsig, batch, N);
    k_final<<<(2 * G * HIDC + 255) / 256, 256>>>(out, G);
}

// round 6
// speedup vs baseline: 2.2569x; 1.0947x over previous
#include <cuda_runtime.h>
#include <cuda_fp16.h>
#include <cstdint>

// Problem constants (dataset-fixed shapes).
static constexpr int NN    = 50000;      // nodes
static constexpr int HIDC  = 64;         // hidden/z dim
static constexpr int INDIM = 128;
static constexpr int N64   = NN * HIDC;  // 3,200,000
static constexpr int ECAP  = 1000000;    // edge capacity (dataset: 800000)
static constexpr int SCAN_BLK = 512;
static constexpr int SCAN_NB  = (NN + SCAN_BLK - 1) / SCAN_BLK;  // 98

// ---- scratch (device globals; no allocations allowed) ----
__device__ int    g_cnt[NN];
__device__ int    g_offs[NN + 1];
__device__ int    g_cursor[NN];
__device__ int    g_bsum[SCAN_NB];
__device__ int    g_srcs[ECAP];
__device__ float  g_w[ECAP];          // per-edge norm = dinv[s]*dinv[d]
__device__ float  g_dinv[NN];
__device__ __half g_XW[N64];          // x @ W1  (fp16 storage, fp32 math)
__device__ __half g_h1[N64];          // ELU(conv1)
__device__ float  g_sums[2 * 64 * 64];
__device__ float  g_cntf[64];

// ---------------- helpers ----------------
__device__ __forceinline__ void red_add_f32x4(float* p, float4 v) {
    asm volatile("red.global.add.v4.f32 [%0], {%1,%2,%3,%4};"
                 :: "l"(p), "f"(v.x), "f"(v.y), "f"(v.z), "f"(v.w) : "memory");
}
__device__ __forceinline__ void red_add_f32(float* p, float v) {
    asm volatile("red.global.add.f32 [%0], %1;" :: "l"(p), "f"(v) : "memory");
}
__device__ __forceinline__ float elu1(float x) { return x > 0.0f ? x : expm1f(x); }
__device__ __forceinline__ float4 elu4(float4 v) {
    v.x = elu1(v.x); v.y = elu1(v.y); v.z = elu1(v.z); v.w = elu1(v.w);
    return v;
}
__device__ __forceinline__ float4 fma4(float4 a, float s, float4 acc) {
    acc.x += a.x * s; acc.y += a.y * s; acc.z += a.z * s; acc.w += a.w * s;
    return acc;
}
__device__ __forceinline__ float4 add4(float4 a, float4 b) {
    a.x += b.x; a.y += b.y; a.z += b.z; a.w += b.w; return a;
}
// accumulate 8 halves (one uint4) scaled by w into acc[8]
__device__ __forceinline__ void fma8h(float* acc, uint4 raw, float w) {
    const __half2* h = reinterpret_cast<const __half2*>(&raw);
#pragma unroll
    for (int j = 0; j < 4; j++) {
        float2 f = __half22float2(h[j]);
        acc[2 * j]     += f.x * w;
        acc[2 * j + 1] += f.y * w;
    }
}
__device__ __forceinline__ uint4 pack8h(const float* a) {
    uint4 out;
    __half2* h = reinterpret_cast<__half2*>(&out);
#pragma unroll
    for (int j = 0; j < 4; j++) h[j] = __floats2half2_rn(a[2 * j], a[2 * j + 1]);
    return out;
}

// CSR gather (fp16 features, fp32 accum): 8 lanes/node, lane owns 8 halves (16B).
__device__ __forceinline__ void csr_gather_h(const __half* __restrict__ F,
                                             int node, int c, float* acc) {
    float acc2[8];
#pragma unroll
    for (int j = 0; j < 8; j++) acc2[j] = 0.f;
    int beg = g_offs[node], end = g_offs[node + 1];
    int k = beg;
    for (; k + 4 <= end; k += 4) {
        int s0 = g_srcs[k + 0], s1 = g_srcs[k + 1];
        int s2 = g_srcs[k + 2], s3 = g_srcs[k + 3];
        float w0 = g_w[k + 0], w1 = g_w[k + 1];
        float w2 = g_w[k + 2], w3 = g_w[k + 3];
        uint4 v0 = *reinterpret_cast<const uint4*>(&F[(long long)s0 * HIDC + c * 8]);
        uint4 v1 = *reinterpret_cast<const uint4*>(&F[(long long)s1 * HIDC + c * 8]);
        uint4 v2 = *reinterpret_cast<const uint4*>(&F[(long long)s2 * HIDC + c * 8]);
        uint4 v3 = *reinterpret_cast<const uint4*>(&F[(long long)s3 * HIDC + c * 8]);
        fma8h(acc,  v0, w0);
        fma8h(acc2, v1, w1);
        fma8h(acc,  v2, w2);
        fma8h(acc2, v3, w3);
    }
    for (; k < end; k++) {
        int s = g_srcs[k];
        float w = g_w[k];
        uint4 v = *reinterpret_cast<const uint4*>(&F[(long long)s * HIDC + c * 8]);
        fma8h(acc, v, w);
    }
#pragma unroll
    for (int j = 0; j < 8; j++) acc[j] += acc2[j];
}

// ---------------- kernels ----------------

__global__ void k_zero() {
    int i = blockIdx.x * blockDim.x + threadIdx.x;
    if (i < NN) g_cnt[i] = 0;
    if (i < 2 * 64 * 64) g_sums[i] = 0.f;
    if (i < 64) g_cntf[i] = 0.f;
}

__global__ void k_deg(const int* __restrict__ dst, int E) {
    int e = blockIdx.x * blockDim.x + threadIdx.x;
    if (e < E) atomicAdd(&g_cnt[dst[e]], 1);
}

// block-local exclusive scan of counts; also dinv and per-block sums.
__global__ void k_scan1(int N) {
    __shared__ int sh[SCAN_BLK];
    int tid = threadIdx.x;
    int i = blockIdx.x * SCAN_BLK + tid;
    int v = (i < N) ? g_cnt[i] : 0;
    if (i < N) g_dinv[i] = rsqrtf((float)v + 1.0f);  // +1 self loop
    sh[tid] = v;
    __syncthreads();
#pragma unroll
    for (int off = 1; off < SCAN_BLK; off <<= 1) {
        int t = (tid >= off) ? sh[tid - off] : 0;
        __syncthreads();
        sh[tid] += t;
        __syncthreads();
    }
    if (i < N) g_offs[i] = sh[tid] - v;
    if (tid == SCAN_BLK - 1) g_bsum[blockIdx.x] = sh[tid];
}

// Adds cross-block prefix (parallel Hillis-Steele over the 98 partials).
__global__ void k_scan3(int N, int E) {
    __shared__ int sb[128];
    int tid = threadIdx.x;
    if (tid < 128) sb[tid] = (tid < SCAN_NB) ? g_bsum[tid] : 0;
    __syncthreads();
#pragma unroll
    for (int off = 1; off < 128; off <<= 1) {
        int t = (tid < 128 && tid >= off) ? sb[tid - off] : 0;
        __syncthreads();
        if (tid < 128) sb[tid] += t;
        __syncthreads();
    }
    int i = blockIdx.x * blockDim.x + tid;
    if (i < N) {
        int blk = i / SCAN_BLK;
        int base = (blk == 0) ? 0 : sb[blk - 1];   // exclusive prefix
        int o = g_offs[i] + base;
        g_offs[i] = o;
        g_cursor[i] = o;
    }
    if (i == 0) g_offs[N] = E;
}

__global__ void k_fill(const int* __restrict__ src, const int* __restrict__ dst, int E) {
    int e = blockIdx.x * blockDim.x + threadIdx.x;
    if (e < E) {
        int d = dst[e];
        int s = src[e];
        int pos = atomicAdd(&g_cursor[d], 1);
        g_srcs[pos] = s;
        g_w[pos] = g_dinv[s] * g_dinv[d];
    }
}

// GEMM1: X[N,128] @ W[128,64] -> g_XW (fp16). 128 rows/block, 256 threads, 8 rows/thread.
__global__ __launch_bounds__(256) void k_gemm1(const float* __restrict__ X,
                                               const float* __restrict__ W, int N) {
    __shared__ float Ws[INDIM * HIDC];
    for (int i = threadIdx.x; i < INDIM * HIDC / 4; i += 256)
        reinterpret_cast<float4*>(Ws)[i] = reinterpret_cast<const float4*>(W)[i];
    __syncthreads();

    const int q  = threadIdx.x & 15;
    const int rg = threadIdx.x >> 4;       // 0..15
    const int row0 = blockIdx.x * 128;

    float4 acc[8];
    int rows[8]; bool valid[8];
#pragma unroll
    for (int rr = 0; rr < 8; rr++) {
        rows[rr] = row0 + rg + 16 * rr;
        valid[rr] = rows[rr] < N;
        acc[rr] = make_float4(0.f, 0.f, 0.f, 0.f);
    }

    for (int k4 = 0; k4 < INDIM / 4; k4++) {
        float4 a[8];
#pragma unroll
        for (int rr = 0; rr < 8; rr++)
            a[rr] = valid[rr]
                ? reinterpret_cast<const float4*>(&X[(long long)rows[rr] * INDIM + k4 * 4])[0]
                : make_float4(0.f, 0.f, 0.f, 0.f);
#pragma unroll
        for (int kk = 0; kk < 4; kk++) {
            float4 w = reinterpret_cast<const float4*>(&Ws[(k4 * 4 + kk) * HIDC + q * 4])[0];
#pragma unroll
            for (int rr = 0; rr < 8; rr++) {
                float av = (&a[rr].x)[kk];
                acc[rr] = fma4(w, av, acc[rr]);
            }
        }
    }
#pragma unroll
    for (int rr = 0; rr < 8; rr++) {
        if (valid[rr]) {
            uint2 p;
            reinterpret_cast<__half2*>(&p)[0] = __floats2half2_rn(acc[rr].x, acc[rr].y);
            reinterpret_cast<__half2*>(&p)[1] = __floats2half2_rn(acc[rr].z, acc[rr].w);
            *reinterpret_cast<uint2*>(&g_XW[(long long)rows[rr] * HIDC + q * 4]) = p;
        }
    }
}

// Layer-1 CSR gather + self-loop + bias + ELU -> g_h1. 8 lanes/node, 8 floats/lane.
__global__ void k_gather1(const float* __restrict__ b1, int N) {
    long long idx = (long long)blockIdx.x * blockDim.x + threadIdx.x;
    if (idx >= (long long)N * 8) return;
    int node = (int)(idx >> 3);
    int c    = (int)(idx & 7);
    float di = g_dinv[node];
    float self = di * di;

    float acc[8];
    {
        uint4 v = *reinterpret_cast<const uint4*>(&g_XW[(long long)node * HIDC + c * 8]);
        const __half2* h = reinterpret_cast<const __half2*>(&v);
#pragma unroll
        for (int j = 0; j < 4; j++) {
            float2 f = __half22float2(h[j]);
            acc[2 * j]     = f.x * self;
            acc[2 * j + 1] = f.y * self;
        }
    }
    csr_gather_h(g_XW, node, c, acc);

#pragma unroll
    for (int j = 0; j < 8; j++) {
        acc[j] += b1[c * 8 + j];
        acc[j] = elu1(acc[j]);
    }
    *reinterpret_cast<uint4*>(&g_h1[(long long)node * HIDC + c * 8]) = pack8h(acc);
}

// Fused layer-2: CSR gather h1 into smem tile (64 nodes), then
// z = tile @ {Wmu,Wsig} + bias, ELU, mean-pool accumulate. 256 threads/block.
__global__ __launch_bounds__(256) void k_gather2gemm2pool(
        const float* __restrict__ Wmu, const float* __restrict__ bmu,
        const float* __restrict__ Wsig, const float* __restrict__ bsig,
        const int* __restrict__ batch, int N) {
    __shared__ float Wms[HIDC * HIDC];
    __shared__ float Wss[HIDC * HIDC];
    __shared__ float tile[64 * HIDC];   // 16 KB
    __shared__ float spool[128];        // 64 mu + 64 sig

    for (int i = threadIdx.x; i < HIDC * HIDC / 4; i += 256) {
        reinterpret_cast<float4*>(Wms)[i] = reinterpret_cast<const float4*>(Wmu)[i];
        reinterpret_cast<float4*>(Wss)[i] = reinterpret_cast<const float4*>(Wsig)[i];
    }
    if (threadIdx.x < 128) spool[threadIdx.x] = 0.f;

    const int row0 = blockIdx.x * 64;

    // ---- Phase A: gather 64 nodes into smem tile (8 lanes/node, 2 nodes/thread) ----
    {
        int c  = threadIdx.x & 7;      // 8-half slice
        int ng = threadIdx.x >> 3;     // 0..31
#pragma unroll
        for (int pp = 0; pp < 2; pp++) {
            int ln = ng + 32 * pp;     // local node 0..63
            int node = row0 + ln;
            float acc[8];
            if (node < N) {
                float di = g_dinv[node];
                float self = di * di;
                uint4 v = *reinterpret_cast<const uint4*>(&g_h1[(long long)node * HIDC + c * 8]);
                const __half2* h = reinterpret_cast<const __half2*>(&v);
#pragma unroll
                for (int j = 0; j < 4; j++) {
                    float2 f = __half22float2(h[j]);
                    acc[2 * j]     = f.x * self;
                    acc[2 * j + 1] = f.y * self;
                }
                csr_gather_h(g_h1, node, c, acc);
            } else {
#pragma unroll
                for (int j = 0; j < 8; j++) acc[j] = 0.f;
            }
            reinterpret_cast<float4*>(&tile[ln * HIDC + c * 8])[0] =
                make_float4(acc[0], acc[1], acc[2], acc[3]);
            reinterpret_cast<float4*>(&tile[ln * HIDC + c * 8 + 4])[0] =
                make_float4(acc[4], acc[5], acc[6], acc[7]);
        }
    }
    __syncthreads();

    // ---- Phase B: dual GEMM from smem + bias + ELU + pool ----
    const int q  = threadIdx.x & 15;
    const int rg = threadIdx.x >> 4;   // 0..15

    float4 am[4], as4[4];
    int rows[4]; bool valid[4];
#pragma unroll
    for (int rr = 0; rr < 4; rr++) {
        rows[rr] = row0 + rg + 16 * rr;
        valid[rr] = rows[rr] < N;
        am[rr]  = make_float4(0.f, 0.f, 0.f, 0.f);
        as4[rr] = make_float4(0.f, 0.f, 0.f, 0.f);
    }

    for (int k4 = 0; k4 < HIDC / 4; k4++) {
        float4 a[4];
#pragma unroll
        for (int rr = 0; rr < 4; rr++)
            a[rr] = reinterpret_cast<const float4*>(&tile[(rg + 16 * rr) * HIDC + k4 * 4])[0];
#pragma unroll
        for (int kk = 0; kk < 4; kk++) {
            float4 wm = reinterpret_cast<const float4*>(&Wms[(k4 * 4 + kk) * HIDC + q * 4])[0];
            float4 ws = reinterpret_cast<const float4*>(&Wss[(k4 * 4 + kk) * HIDC + q * 4])[0];
#pragma unroll
            for (int rr = 0; rr < 4; rr++) {
                float av = (&a[rr].x)[kk];
                am[rr]  = fma4(wm, av, am[rr]);
                as4[rr] = fma4(ws, av, as4[rr]);
            }
        }
    }

    float4 bbm = reinterpret_cast<const float4*>(&bmu[q * 4])[0];
    float4 bbs = reinterpret_cast<const float4*>(&bsig[q * 4])[0];
#pragma unroll
    for (int rr = 0; rr < 4; rr++) {
        am[rr]  = elu4(add4(am[rr], bbm));
        as4[rr] = elu4(add4(as4[rr], bbs));
    }

    int lastRow = min(row0 + 63, N - 1);
    int g0 = batch[row0];
    int g1 = batch[lastRow];

    if (g0 == g1) {
        float4 sm = make_float4(0.f, 0.f, 0.f, 0.f);
        float4 ss = make_float4(0.f, 0.f, 0.f, 0.f);
#pragma unroll
        for (int rr = 0; rr < 4; rr++) {
            if (valid[rr]) { sm = add4(sm, am[rr]); ss = add4(ss, as4[rr]); }
        }
        atomicAdd(&spool[q * 4 + 0], sm.x);
        atomicAdd(&spool[q * 4 + 1], sm.y);
        atomicAdd(&spool[q * 4 + 2], sm.z);
        atomicAdd(&spool[q * 4 + 3], sm.w);
        atomicAdd(&spool[64 + q * 4 + 0], ss.x);
        atomicAdd(&spool[64 + q * 4 + 1], ss.y);
        atomicAdd(&spool[64 + q * 4 + 2], ss.z);
        atomicAdd(&spool[64 + q * 4 + 3], ss.w);
        __syncthreads();
        if (threadIdx.x < 32) {
            int half = threadIdx.x >> 4;
            int cc   = threadIdx.x & 15;
            float4 v = reinterpret_cast<const float4*>(&spool[half * 64 + cc * 4])[0];
            red_add_f32x4(&g_sums[(long long)(half * 64 + g0) * HIDC + cc * 4], v);
        }
        if (threadIdx.x == 0) {
            int cnt = min(N - row0, 64);
            red_add_f32(&g_cntf[g0], (float)cnt);
        }
    } else {
#pragma unroll
        for (int rr = 0; rr < 4; rr++) {
            if (!valid[rr]) continue;
            int g = batch[rows[rr]];
            red_add_f32x4(&g_sums[(long long)(0 * 64 + g) * HIDC + q * 4], am[rr]);
            red_add_f32x4(&g_sums[(long long)(1 * 64 + g) * HIDC + q * 4], as4[rr]);
            if (q == 0) red_add_f32(&g_cntf[g], 1.0f);
        }
    }
}

// Final: divide by counts, write [z_mu ; z_sigma] to d_out.
__global__ void k_final(float* __restrict__ out, int G) {
    int tid = blockIdx.x * blockDim.x + threadIdx.x;
    int total = 2 * G * HIDC;
    if (tid >= total) return;
    int t = tid / (G * HIDC);
    int rem = tid - t * G * HIDC;
    int g = rem >> 6;
    int c = rem & 63;
    float cnt = fmaxf(g_cntf[g], 1.0f);
    out[tid] = g_sums[(long long)(t * 64 + g) * HIDC + c] / cnt;
}

// ---------------- launch ----------------
extern "C" void kernel_launch(void* const* d_in, const int* in_sizes, int n_in,
                              void* d_out, int out_size) {
    const float* x     = (const float*)d_in[0];
    const int*   ei    = (const int*)d_in[1];
    const int*   batch = (const int*)d_in[2];

    int N = in_sizes[0] / INDIM;   // 50000
    int E = in_sizes[1] / 2;       // 800000
    int G = out_size / (2 * HIDC); // 64

    int wi = 3;
    if (in_sizes[3] == 1) wi = 4;  // num_graphs may be materialized
    const float* W1   = (const float*)d_in[wi + 0];
    const float* b1   = (const float*)d_in[wi + 1];
    const float* Wmu  = (const float*)d_in[wi + 2];
    const float* bmu  = (const float*)d_in[wi + 3];
    const float* Wsig = (const float*)d_in[wi + 4];
    const float* bsig = (const float*)d_in[wi + 5];
    float* out = (float*)d_out;

    const int* src = ei;
    const int* dst = ei + E;

    k_zero<<<(NN + 255) / 256, 256>>>();
    k_deg<<<(E + 255) / 256, 256>>>(dst, E);
    k_scan1<<<SCAN_NB, SCAN_BLK>>>(N);
    k_scan3<<<(N + 255) / 256, 256>>>(N, E);
    k_fill<<<(E + 255) / 256, 256>>>(src, dst, E);
    k_gemm1<<<(N + 127) / 128, 256>>>(x, W1, N);
    {
        long long t = (long long)N * 8;
        k_gather1<<<(unsigned)((t + 255) / 256), 256>>>(b1, N);
    }
    k_gather2gemm2pool<<<(N + 63) / 64, 256>>>(Wmu, bmu, Wsig, bsig, batch, N);
    k_final<<<(2 * G * HIDC + 255) / 256, 256>>>(out, G);
}